// round 14
// baseline (speedup 1.0000x reference)
#include <cuda_runtime.h>
#include <cstdint>

#define S_LEN 4096
#define HID   2048
#define QKV_LD 3072
#define WIN_  1024
#define SCALE_F 0.08838834764831845f   // 128^-0.5

static __device__ float g_qkv [S_LEN * QKV_LD];   // [s][ q(16*128) | k(4*128) | v(4*128) ]
static __device__ float g_attn[S_LEN * HID];      // attn out (tf32-rounded at store)
static __device__ float g_hid_r[S_LEN * HID];     // tf32-rounded hidden
static __device__ float g_w_r[(2048 + 512 + 512 + 2048) * HID];  // wq|wk|wv|wo rounded

#define WQ_OFF 0
#define WK_OFF (2048 * HID)
#define WV_OFF (2560 * HID)
#define WO_OFF (3072 * HID)

// ---------------------------------------------------------------------------
// helpers
// ---------------------------------------------------------------------------
__device__ __forceinline__ float to_tf32(float x) {
    unsigned u;
    asm("cvt.rna.tf32.f32 %0, %1;" : "=r"(u) : "f"(x));
    return __uint_as_float(u);
}
__device__ __forceinline__ unsigned fu(float x) { return __float_as_uint(x); }

__device__ __forceinline__ uint32_t smem_u32(const void* p) {
    uint32_t a;
    asm("{ .reg .u64 t; cvta.to.shared.u64 t, %1; cvt.u32.u64 %0, t; }"
        : "=r"(a) : "l"(p));
    return a;
}

#define CP_ASYNC16(saddr, gptr) \
    asm volatile("cp.async.cg.shared.global [%0], [%1], 16;" \
        :: "r"((uint32_t)(saddr)), "l"(gptr) : "memory")
#define CP_COMMIT() asm volatile("cp.async.commit_group;" ::: "memory")
#define CP_WAIT(n)  asm volatile("cp.async.wait_group %0;" :: "n"(n) : "memory")

#define LDSM_X4(r0, r1, r2, r3, addr) \
    asm volatile("ldmatrix.sync.aligned.m8n8.x4.shared.b16 {%0,%1,%2,%3}, [%4];" \
        : "=r"(r0), "=r"(r1), "=r"(r2), "=r"(r3) : "r"(addr))
#define LDSM_X2(r0, r1, addr) \
    asm volatile("ldmatrix.sync.aligned.m8n8.x2.shared.b16 {%0,%1}, [%2];" \
        : "=r"(r0), "=r"(r1) : "r"(addr))

// D(16x8) += A(16x8) * B(8x8)^T, tf32
__device__ __forceinline__ void mma_tf32(float* c, const unsigned* a, const unsigned* b) {
    asm volatile(
        "mma.sync.aligned.m16n8k8.row.col.f32.tf32.tf32.f32 "
        "{%0,%1,%2,%3}, {%4,%5,%6,%7}, {%8,%9}, {%0,%1,%2,%3};\n"
        : "+f"(c[0]), "+f"(c[1]), "+f"(c[2]), "+f"(c[3])
        : "r"(a[0]), "r"(a[1]), "r"(a[2]), "r"(a[3]), "r"(b[0]), "r"(b[1]));
}

// ===========================================================================
// Fused elementwise tf32 pre-rounding over 5 segments (one launch)
// ===========================================================================
__global__ __launch_bounds__(256)
void round_all(const float4* s0, float4* d0, int n0,
               const float4* s1, float4* d1, int n1,
               const float4* s2, float4* d2, int n2,
               const float4* s3, float4* d3, int n3,
               const float4* s4, float4* d4, int n4)
{
    int i = blockIdx.x * 256 + threadIdx.x;
    const float4* src; float4* dst;
    if (i < n0)                            { src = s0; dst = d0; }
    else if ((i -= n0) < n1)               { src = s1; dst = d1; }
    else if ((i -= n1) < n2)               { src = s2; dst = d2; }
    else if ((i -= n2) < n3)               { src = s3; dst = d3; }
    else if ((i -= n3) < n4)               { src = s4; dst = d4; }
    else return;
    float4 v = src[i];
    v.x = to_tf32(v.x); v.y = to_tf32(v.y);
    v.z = to_tf32(v.z); v.w = to_tf32(v.w);
    dst[i] = v;
}

// ===========================================================================
// GEMM:  C[:, cout..] = A[M,K] * B[128 rows, K]^T   (inputs PRE-ROUNDED tf32)
// BM=128, BN=128, BK=32; 256 threads = 8 warps (2M x 4N), warp tile 64x32.
// 3-stage cp.async pipeline with CP_WAIT(1); 110.6 KB smem -> 2 CTAs/SM.
// Per-block weight select fuses Q/K/V projections into one launch.
// ===========================================================================
#define BK    32
#define STG   3
#define GP    36                        // smem row pitch in floats (144 B; 144%128==16)
#define ROWB  (GP * 4)
#define A_BYT (128 * ROWB)              // 18432
#define B_BYT (128 * ROWB)              // 18432
#define STBYT (A_BYT + B_BYT)           // 36864 B / stage
#define GEMM_SMEM (STG * STBYT)         // 110592 B

__global__ __launch_bounds__(256, 2)
void gemm_cp(const float* __restrict__ A, int lda,
             const float* __restrict__ B0, const float* __restrict__ B1,
             const float* __restrict__ B2, int ldb,
             float* __restrict__ C, int ldc, int K, int nb0, int nb1)
{
    extern __shared__ char sm[];
    const uint32_t sb = smem_u32(sm);
    const int tid = threadIdx.x;
    const int w = tid >> 5, lane = tid & 31;
    const int g = lane >> 2, qd = lane & 3;
    const int wm = (w & 1) * 64;
    const int wn = (w >> 1) * 32;
    const int bm = blockIdx.y * 128;

    const int bx = blockIdx.x;
    const float* B;
    int cout;
    if (bx < nb0)            { B = B0 + (long)(bx * 128) * ldb;               cout = bx * 128; }
    else if (bx < nb0 + nb1) { B = B1 + (long)((bx - nb0) * 128) * ldb;       cout = nb0 * 128 + (bx - nb0) * 128; }
    else                     { B = B2 + (long)((bx - nb0 - nb1) * 128) * ldb; cout = (nb0 + nb1) * 128 + (bx - nb0 - nb1) * 128; }

    float acc[4][4][4];
    #pragma unroll
    for (int mt = 0; mt < 4; mt++)
        #pragma unroll
        for (int nt = 0; nt < 4; nt++)
            #pragma unroll
            for (int e = 0; e < 4; e++) acc[mt][nt][e] = 0.f;

    const int lr = tid >> 3;           // 0..31
    const int lc = tid & 7;            // 16B chunk within 32-float row

    const int at  = lane >> 3;
    const int art = lane & 7;
    const uint32_t aoff = (uint32_t)((wm + (at & 1) * 8 + art) * ROWB + ((at >> 1) * 4) * 4);
    const int btile = (lane >> 3) & 1;
    const uint32_t boff = (uint32_t)((wn + art) * ROWB + (btile * 4) * 4) + A_BYT;

    const int niter = K / BK;          // 64

    // ---- prologue: stages 0 and 1 ----
    #pragma unroll
    for (int s = 0; s < STG - 1; s++) {
        const uint32_t ab = sb + s * STBYT;
        const uint32_t bb = ab + A_BYT;
        const int kk = s * BK;
        #pragma unroll
        for (int i = 0; i < 4; i++) {
            const int r = lr + 32 * i;
            CP_ASYNC16(ab + r * ROWB + lc * 16, A + (long)(bm + r) * lda + kk + lc * 4);
        }
        #pragma unroll
        for (int i = 0; i < 4; i++) {
            const int r = lr + 32 * i;
            CP_ASYNC16(bb + r * ROWB + lc * 16, B + (long)r * ldb + kk + lc * 4);
        }
        CP_COMMIT();
    }

    for (int it = 0; it < niter; it++) {
        CP_WAIT(1);            // stage 'it' complete; stage 'it+1' may be in flight
        __syncthreads();       // all warps done with stage 'it-1' buffer

        const int nxt = it + 2;
        if (nxt < niter) {
            const int s = nxt % STG;
            const uint32_t ab = sb + s * STBYT;
            const uint32_t bb = ab + A_BYT;
            const int kk = nxt * BK;
            #pragma unroll
            for (int i = 0; i < 4; i++) {
                const int r = lr + 32 * i;
                CP_ASYNC16(ab + r * ROWB + lc * 16, A + (long)(bm + r) * lda + kk + lc * 4);
            }
            #pragma unroll
            for (int i = 0; i < 4; i++) {
                const int r = lr + 32 * i;
                CP_ASYNC16(bb + r * ROWB + lc * 16, B + (long)r * ldb + kk + lc * 4);
            }
        }
        CP_COMMIT();           // uniform one commit per iter

        const uint32_t stage = sb + (it % STG) * STBYT;
        const uint32_t aBase = stage + aoff;
        const uint32_t bBase = stage + boff;

        #pragma unroll
        for (int kk = 0; kk < BK; kk += 8) {
            unsigned af[4][4], bf[4][2];
            #pragma unroll
            for (int mt = 0; mt < 4; mt++)
                LDSM_X4(af[mt][0], af[mt][1], af[mt][2], af[mt][3],
                        aBase + (uint32_t)(mt * 16 * ROWB + kk * 4));
            #pragma unroll
            for (int nt = 0; nt < 4; nt++)
                LDSM_X2(bf[nt][0], bf[nt][1],
                        bBase + (uint32_t)(nt * 8 * ROWB + kk * 4));
            #pragma unroll
            for (int mt = 0; mt < 4; mt++)
                #pragma unroll
                for (int nt = 0; nt < 4; nt++)
                    mma_tf32(acc[mt][nt], af[mt], bf[nt]);
        }
    }

    #pragma unroll
    for (int mt = 0; mt < 4; mt++) {
        const int r0 = bm + wm + mt * 16 + g;
        #pragma unroll
        for (int nt = 0; nt < 4; nt++) {
            const int cc = cout + wn + nt * 8 + 2 * qd;
            *(float2*)&C[(long)r0 * ldc + cc] =
                make_float2(acc[mt][nt][0], acc[mt][nt][1]);
            *(float2*)&C[(long)(r0 + 8) * ldc + cc] =
                make_float2(acc[mt][nt][2], acc[mt][nt][3]);
        }
    }
}

// ===========================================================================
// RoPE (in-place): tmp = concat(x[64:], x[:64]), NO negation.
// ===========================================================================
__global__ __launch_bounds__(256)
void rope_kernel(const float* __restrict__ cosb, const float* __restrict__ sinb)
{
    const int s = blockIdx.x;
    const float* cs = cosb + s * 128;
    const float* sn = sinb + s * 128;
    float* row = g_qkv + (long)s * QKV_LD;
    for (int p = threadIdx.x; p < 20 * 64; p += 256) {
        const int head = p >> 6;
        const int d = p & 63;
        float* base = row + head * 128;
        float x0 = base[d];
        float x1 = base[d + 64];
        base[d]      = x0 * cs[d]      + x1 * sn[d];
        base[d + 64] = x1 * cs[d + 64] + x0 * sn[d + 64];
    }
}

// ===========================================================================
// Sliding-window flash attention, tf32 mma.sync.
// Post-softmax CTA barrier demoted to __syncwarp (Ps rows are warp-private).
// grid (16 heads, 32 q-blocks of 128), 256 threads = 8 warps.
// ===========================================================================
#define QP 132
#define KP 132
#define VP 136
#define PP 68
#define ATTN_SMEM ((128 * QP + 64 * KP + 64 * VP + 128 * PP) * 4)

__global__ __launch_bounds__(256, 1)
void attn_tf32()
{
    extern __shared__ float smf[];
    float* Qs = smf;                // [128][QP]
    float* Ks = Qs + 128 * QP;      // [64][KP]
    float* Vs = Ks + 64 * KP;       // [64][VP]
    float* Ps = Vs + 64 * VP;       // [128][PP]

    const int h  = blockIdx.x;
    const int q0 = (int)(gridDim.y - 1 - blockIdx.y) * 128;
    const int kvh = h >> 2;
    const int tid = threadIdx.x;
    const int w = tid >> 5, lane = tid & 31;
    const int g = lane >> 2, qd = lane & 3;
    const int wm = w * 16;

    for (int idx = tid; idx < 128 * 32; idx += 256) {
        int r = idx >> 5, c = (idx & 31) * 4;
        float4 v = *(const float4*)(g_qkv + (long)(q0 + r) * QKV_LD + h * 128 + c);
        float* q = Qs + r * QP + c;
        q[0] = to_tf32(v.x * SCALE_F); q[1] = to_tf32(v.y * SCALE_F);
        q[2] = to_tf32(v.z * SCALE_F); q[3] = to_tf32(v.w * SCALE_F);
    }

    float o[16][4];
    #pragma unroll
    for (int nt = 0; nt < 16; nt++)
        #pragma unroll
        for (int e = 0; e < 4; e++) o[nt][e] = 0.f;
    float m0 = -1e30f, m1 = -1e30f, l0 = 0.f, l1 = 0.f;

    const int kstart = (q0 >= WIN_) ? q0 - WIN_ : 0;
    const int kend   = q0 + 64;

    for (int k0 = kstart; k0 <= kend; k0 += 64) {
        __syncthreads();   // prior iteration done reading Ks/Vs
        for (int idx = tid; idx < 64 * 32; idx += 256) {
            int r = idx >> 5, c = (idx & 31) * 4;
            const float* src = g_qkv + (long)(k0 + r) * QKV_LD + 2048 + kvh * 128 + c;
            float4 kv = *(const float4*)src;
            float4 vv = *(const float4*)(src + 512);
            float* kd = Ks + r * KP + c;
            kd[0] = to_tf32(kv.x); kd[1] = to_tf32(kv.y);
            kd[2] = to_tf32(kv.z); kd[3] = to_tf32(kv.w);
            float* vd = Vs + r * VP + c;
            vd[0] = to_tf32(vv.x); vd[1] = to_tf32(vv.y);
            vd[2] = to_tf32(vv.z); vd[3] = to_tf32(vv.w);
        }
        __syncthreads();

        float s[8][4];
        #pragma unroll
        for (int nt = 0; nt < 8; nt++)
            #pragma unroll
            for (int e = 0; e < 4; e++) s[nt][e] = 0.f;

        #pragma unroll
        for (int kk = 0; kk < 128; kk += 8) {
            unsigned af[4];
            af[0] = fu(Qs[(wm + g) * QP + kk + qd]);
            af[1] = fu(Qs[(wm + g + 8) * QP + kk + qd]);
            af[2] = fu(Qs[(wm + g) * QP + kk + qd + 4]);
            af[3] = fu(Qs[(wm + g + 8) * QP + kk + qd + 4]);
            #pragma unroll
            for (int nt = 0; nt < 8; nt++) {
                unsigned bf[2];
                bf[0] = fu(Ks[(nt * 8 + g) * KP + kk + qd]);
                bf[1] = fu(Ks[(nt * 8 + g) * KP + kk + qd + 4]);
                mma_tf32(s[nt], af, bf);
            }
        }

        const int r0 = q0 + wm + g, r1 = r0 + 8;
        float mx0 = -1e30f, mx1 = -1e30f;
        #pragma unroll
        for (int nt = 0; nt < 8; nt++) {
            const int j0 = k0 + nt * 8 + 2 * qd;
            const int j1 = j0 + 1;
            if (!(j0 <= r0 && (r0 - j0) < WIN_)) s[nt][0] = -1e30f;
            if (!(j1 <= r0 && (r0 - j1) < WIN_)) s[nt][1] = -1e30f;
            if (!(j0 <= r1 && (r1 - j0) < WIN_)) s[nt][2] = -1e30f;
            if (!(j1 <= r1 && (r1 - j1) < WIN_)) s[nt][3] = -1e30f;
            mx0 = fmaxf(mx0, fmaxf(s[nt][0], s[nt][1]));
            mx1 = fmaxf(mx1, fmaxf(s[nt][2], s[nt][3]));
        }
        mx0 = fmaxf(mx0, __shfl_xor_sync(0xffffffffu, mx0, 1));
        mx0 = fmaxf(mx0, __shfl_xor_sync(0xffffffffu, mx0, 2));
        mx1 = fmaxf(mx1, __shfl_xor_sync(0xffffffffu, mx1, 1));
        mx1 = fmaxf(mx1, __shfl_xor_sync(0xffffffffu, mx1, 2));

        const float mn0 = fmaxf(m0, mx0), mn1 = fmaxf(m1, mx1);
        const float sc0 = __expf(m0 - mn0), sc1 = __expf(m1 - mn1);
        float rs0 = 0.f, rs1 = 0.f;
        #pragma unroll
        for (int nt = 0; nt < 8; nt++) {
            float p0 = __expf(s[nt][0] - mn0);
            float p1 = __expf(s[nt][1] - mn0);
            float p2 = __expf(s[nt][2] - mn1);
            float p3 = __expf(s[nt][3] - mn1);
            rs0 += p0 + p1; rs1 += p2 + p3;
            *(float2*)&Ps[(wm + g) * PP + nt * 8 + 2 * qd] =
                make_float2(to_tf32(p0), to_tf32(p1));
            *(float2*)&Ps[(wm + g + 8) * PP + nt * 8 + 2 * qd] =
                make_float2(to_tf32(p2), to_tf32(p3));
        }
        rs0 += __shfl_xor_sync(0xffffffffu, rs0, 1);
        rs0 += __shfl_xor_sync(0xffffffffu, rs0, 2);
        rs1 += __shfl_xor_sync(0xffffffffu, rs1, 1);
        rs1 += __shfl_xor_sync(0xffffffffu, rs1, 2);

        l0 = l0 * sc0 + rs0; l1 = l1 * sc1 + rs1;
        m0 = mn0; m1 = mn1;
        #pragma unroll
        for (int nt = 0; nt < 16; nt++) {
            o[nt][0] *= sc0; o[nt][1] *= sc0;
            o[nt][2] *= sc1; o[nt][3] *= sc1;
        }
        __syncwarp();      // Ps rows are warp-private; cross-lane visibility only

        #pragma unroll
        for (int kk = 0; kk < 64; kk += 8) {
            unsigned pa[4];
            pa[0] = fu(Ps[(wm + g) * PP + kk + qd]);
            pa[1] = fu(Ps[(wm + g + 8) * PP + kk + qd]);
            pa[2] = fu(Ps[(wm + g) * PP + kk + qd + 4]);
            pa[3] = fu(Ps[(wm + g + 8) * PP + kk + qd + 4]);
            #pragma unroll
            for (int nt = 0; nt < 16; nt++) {
                unsigned bf[2];
                bf[0] = fu(Vs[(kk + qd) * VP + nt * 8 + g]);
                bf[1] = fu(Vs[(kk + qd + 4) * VP + nt * 8 + g]);
                mma_tf32(o[nt], pa, bf);
            }
        }
    }

    // epilogue: normalize AND pre-round to tf32 for the O-projection
    const float i0 = 1.f / l0, i1 = 1.f / l1;
    const int rr0 = q0 + wm + g;
    #pragma unroll
    for (int nt = 0; nt < 16; nt++) {
        const int cc = h * 128 + nt * 8 + 2 * qd;
        *(float2*)&g_attn[(long)rr0 * HID + cc] =
            make_float2(to_tf32(o[nt][0] * i0), to_tf32(o[nt][1] * i0));
        *(float2*)&g_attn[(long)(rr0 + 8) * HID + cc] =
            make_float2(to_tf32(o[nt][2] * i1), to_tf32(o[nt][3] * i1));
    }
}

// ===========================================================================
// Launch
// ===========================================================================
extern "C" void kernel_launch(void* const* d_in, const int* in_sizes, int n_in,
                              void* d_out, int out_size)
{
    (void)in_sizes; (void)n_in; (void)out_size;
    const float* hidden = (const float*)d_in[0];
    const float* wq = (const float*)d_in[1];
    const float* wk = (const float*)d_in[2];
    const float* wv = (const float*)d_in[3];
    const float* wo = (const float*)d_in[4];
    const float* cosb = (const float*)d_in[5];
    const float* sinb = (const float*)d_in[6];
    float* out = (float*)d_out;

    void *qkvp, *attnp, *hidrp, *wrp;
    cudaGetSymbolAddress(&qkvp,  g_qkv);
    cudaGetSymbolAddress(&attnp, g_attn);
    cudaGetSymbolAddress(&hidrp, g_hid_r);
    cudaGetSymbolAddress(&wrp,   g_w_r);
    float* qkv   = (float*)qkvp;
    float* attn  = (float*)attnp;
    float* hid_r = (float*)hidrp;
    float* w_r   = (float*)wrp;

    static int attrs_set = 0;
    if (!attrs_set) {
        cudaFuncSetAttribute(gemm_cp,   cudaFuncAttributeMaxDynamicSharedMemorySize, GEMM_SMEM);
        cudaFuncSetAttribute(attn_tf32, cudaFuncAttributeMaxDynamicSharedMemorySize, ATTN_SMEM);
        attrs_set = 1;
    }

    // single fused pre-rounding pass over hidden + 4 weight matrices
    {
        const int n_hid = S_LEN * HID / 4;          // 2,097,152
        const int n_wq  = 2048 * HID / 4;           // 1,048,576
        const int n_wkv = 512 * HID / 4;            // 262,144
        const int total = n_hid + n_wq + 2 * n_wkv + n_wq;
        round_all<<<(total + 255) / 256, 256>>>(
            (const float4*)hidden, (float4*)hid_r, n_hid,
            (const float4*)wq, (float4*)(w_r + WQ_OFF), n_wq,
            (const float4*)wk, (float4*)(w_r + WK_OFF), n_wkv,
            (const float4*)wv, (float4*)(w_r + WV_OFF), n_wkv,
            (const float4*)wo, (float4*)(w_r + WO_OFF), n_wq);
    }

    // fused QKV projection: 128-col blocks; wq 16, wk 4, wv 4
    gemm_cp<<<dim3(24, 32), 256, GEMM_SMEM>>>(hid_r, HID,
                                              w_r + WQ_OFF, w_r + WK_OFF, w_r + WV_OFF, HID,
                                              qkv, QKV_LD, HID, 16, 4);

    // RoPE on q and k
    rope_kernel<<<S_LEN, 256>>>(cosb, sinb);

    // sliding-window attention (mma.sync tf32)
    attn_tf32<<<dim3(16, 32), 256, ATTN_SMEM>>>();

    // output projection
    gemm_cp<<<dim3(16, 32), 256, GEMM_SMEM>>>(attn, HID,
                                              w_r + WO_OFF, w_r + WO_OFF, w_r + WO_OFF, HID,
                                              out, HID, HID, 16, 0);
}

// round 15
// speedup vs baseline: 1.0276x; 1.0276x over previous
#include <cuda_runtime.h>
#include <cstdint>

#define S_LEN 4096
#define HID   2048
#define QKV_LD 3072
#define WIN_  1024
#define SCALE_F 0.08838834764831845f   // 128^-0.5

static __device__ float g_qkv [S_LEN * QKV_LD];   // [s][ q(16*128) | k(4*128) | v(4*128) ]
static __device__ float g_attn[S_LEN * HID];      // attn out (tf32-rounded at store)
static __device__ float g_hid_r[S_LEN * HID];     // tf32-rounded hidden
static __device__ float g_w_r[(2048 + 512 + 512 + 2048) * HID];  // wq|wk|wv|wo rounded

#define WQ_OFF 0
#define WK_OFF (2048 * HID)
#define WV_OFF (2560 * HID)
#define WO_OFF (3072 * HID)

// ---------------------------------------------------------------------------
// helpers
// ---------------------------------------------------------------------------
__device__ __forceinline__ float to_tf32(float x) {
    unsigned u;
    asm("cvt.rna.tf32.f32 %0, %1;" : "=r"(u) : "f"(x));
    return __uint_as_float(u);
}
__device__ __forceinline__ unsigned fu(float x) { return __float_as_uint(x); }

__device__ __forceinline__ uint32_t smem_u32(const void* p) {
    uint32_t a;
    asm("{ .reg .u64 t; cvta.to.shared.u64 t, %1; cvt.u32.u64 %0, t; }"
        : "=r"(a) : "l"(p));
    return a;
}

#define CP_ASYNC16(saddr, gptr) \
    asm volatile("cp.async.cg.shared.global [%0], [%1], 16;" \
        :: "r"((uint32_t)(saddr)), "l"(gptr) : "memory")
#define CP_COMMIT() asm volatile("cp.async.commit_group;" ::: "memory")
#define CP_WAIT(n)  asm volatile("cp.async.wait_group %0;" :: "n"(n) : "memory")

#define LDSM_X4(r0, r1, r2, r3, addr) \
    asm volatile("ldmatrix.sync.aligned.m8n8.x4.shared.b16 {%0,%1,%2,%3}, [%4];" \
        : "=r"(r0), "=r"(r1), "=r"(r2), "=r"(r3) : "r"(addr))
#define LDSM_X2(r0, r1, addr) \
    asm volatile("ldmatrix.sync.aligned.m8n8.x2.shared.b16 {%0,%1}, [%2];" \
        : "=r"(r0), "=r"(r1) : "r"(addr))

// D(16x8) += A(16x8) * B(8x8)^T, tf32
__device__ __forceinline__ void mma_tf32(float* c, const unsigned* a, const unsigned* b) {
    asm volatile(
        "mma.sync.aligned.m16n8k8.row.col.f32.tf32.tf32.f32 "
        "{%0,%1,%2,%3}, {%4,%5,%6,%7}, {%8,%9}, {%0,%1,%2,%3};\n"
        : "+f"(c[0]), "+f"(c[1]), "+f"(c[2]), "+f"(c[3])
        : "r"(a[0]), "r"(a[1]), "r"(a[2]), "r"(a[3]), "r"(b[0]), "r"(b[1]));
}

// ===========================================================================
// Fused elementwise tf32 pre-rounding over 5 segments (one launch)
// ===========================================================================
__global__ __launch_bounds__(256)
void round_all(const float4* s0, float4* d0, int n0,
               const float4* s1, float4* d1, int n1,
               const float4* s2, float4* d2, int n2,
               const float4* s3, float4* d3, int n3,
               const float4* s4, float4* d4, int n4)
{
    int i = blockIdx.x * 256 + threadIdx.x;
    const float4* src; float4* dst;
    if (i < n0)                            { src = s0; dst = d0; }
    else if ((i -= n0) < n1)               { src = s1; dst = d1; }
    else if ((i -= n1) < n2)               { src = s2; dst = d2; }
    else if ((i -= n2) < n3)               { src = s3; dst = d3; }
    else if ((i -= n3) < n4)               { src = s4; dst = d4; }
    else return;
    float4 v = src[i];
    v.x = to_tf32(v.x); v.y = to_tf32(v.y);
    v.z = to_tf32(v.z); v.w = to_tf32(v.w);
    dst[i] = v;
}

// ===========================================================================
// GEMM (R13-proven):  C[:, cout..] = A[M,K] * B[128 rows, K]^T
// BM=128, BN=128, BK=32; 256 threads = 8 warps (2M x 4N), warp tile 64x32.
// 2-stage cp.async ping-pong, 73.7 KB smem -> 2 CTAs/SM.
// ===========================================================================
#define BK    32
#define GP    36                        // smem row pitch in floats (144 B; 144%128==16)
#define ROWB  (GP * 4)
#define A_BYT (128 * ROWB)
#define B_BYT (128 * ROWB)
#define STBYT (A_BYT + B_BYT)
#define GEMM_SMEM (2 * STBYT)           // 73728 B

__global__ __launch_bounds__(256, 2)
void gemm_cp(const float* __restrict__ A, int lda,
             const float* __restrict__ B0, const float* __restrict__ B1,
             const float* __restrict__ B2, int ldb,
             float* __restrict__ C, int ldc, int K, int nb0, int nb1)
{
    extern __shared__ char sm[];
    const uint32_t sb = smem_u32(sm);
    const int tid = threadIdx.x;
    const int w = tid >> 5, lane = tid & 31;
    const int g = lane >> 2, qd = lane & 3;
    const int wm = (w & 1) * 64;
    const int wn = (w >> 1) * 32;
    const int bm = blockIdx.y * 128;

    const int bx = blockIdx.x;
    const float* B;
    int cout;
    if (bx < nb0)            { B = B0 + (long)(bx * 128) * ldb;               cout = bx * 128; }
    else if (bx < nb0 + nb1) { B = B1 + (long)((bx - nb0) * 128) * ldb;       cout = nb0 * 128 + (bx - nb0) * 128; }
    else                     { B = B2 + (long)((bx - nb0 - nb1) * 128) * ldb; cout = (nb0 + nb1) * 128 + (bx - nb0 - nb1) * 128; }

    float acc[4][4][4];
    #pragma unroll
    for (int mt = 0; mt < 4; mt++)
        #pragma unroll
        for (int nt = 0; nt < 4; nt++)
            #pragma unroll
            for (int e = 0; e < 4; e++) acc[mt][nt][e] = 0.f;

    const int lr = tid >> 3;
    const int lc = tid & 7;

    const int at  = lane >> 3;
    const int art = lane & 7;
    const uint32_t aoff = (uint32_t)((wm + (at & 1) * 8 + art) * ROWB + ((at >> 1) * 4) * 4);
    const int btile = (lane >> 3) & 1;
    const uint32_t boff = (uint32_t)((wn + art) * ROWB + (btile * 4) * 4) + A_BYT;

    const int niter = K / BK;

    {
        const uint32_t ab = sb;
        const uint32_t bb = sb + A_BYT;
        #pragma unroll
        for (int i = 0; i < 4; i++) {
            const int r = lr + 32 * i;
            CP_ASYNC16(ab + r * ROWB + lc * 16, A + (long)(bm + r) * lda + lc * 4);
        }
        #pragma unroll
        for (int i = 0; i < 4; i++) {
            const int r = lr + 32 * i;
            CP_ASYNC16(bb + r * ROWB + lc * 16, B + (long)r * ldb + lc * 4);
        }
        CP_COMMIT();
    }

    for (int it = 0; it < niter; it++) {
        CP_WAIT(0);
        __syncthreads();

        const int nxt = it + 1;
        if (nxt < niter) {
            const uint32_t ab = sb + (nxt & 1) * STBYT;
            const uint32_t bb = ab + A_BYT;
            const int kk = nxt * BK;
            #pragma unroll
            for (int i = 0; i < 4; i++) {
                const int r = lr + 32 * i;
                CP_ASYNC16(ab + r * ROWB + lc * 16, A + (long)(bm + r) * lda + kk + lc * 4);
            }
            #pragma unroll
            for (int i = 0; i < 4; i++) {
                const int r = lr + 32 * i;
                CP_ASYNC16(bb + r * ROWB + lc * 16, B + (long)r * ldb + kk + lc * 4);
            }
            CP_COMMIT();
        }

        const uint32_t stage = sb + (it & 1) * STBYT;
        const uint32_t aBase = stage + aoff;
        const uint32_t bBase = stage + boff;

        #pragma unroll
        for (int kk = 0; kk < BK; kk += 8) {
            unsigned af[4][4], bf[4][2];
            #pragma unroll
            for (int mt = 0; mt < 4; mt++)
                LDSM_X4(af[mt][0], af[mt][1], af[mt][2], af[mt][3],
                        aBase + (uint32_t)(mt * 16 * ROWB + kk * 4));
            #pragma unroll
            for (int nt = 0; nt < 4; nt++)
                LDSM_X2(bf[nt][0], bf[nt][1],
                        bBase + (uint32_t)(nt * 8 * ROWB + kk * 4));
            #pragma unroll
            for (int mt = 0; mt < 4; mt++)
                #pragma unroll
                for (int nt = 0; nt < 4; nt++)
                    mma_tf32(acc[mt][nt], af[mt], bf[nt]);
        }
    }

    #pragma unroll
    for (int mt = 0; mt < 4; mt++) {
        const int r0 = bm + wm + mt * 16 + g;
        #pragma unroll
        for (int nt = 0; nt < 4; nt++) {
            const int cc = cout + wn + nt * 8 + 2 * qd;
            *(float2*)&C[(long)r0 * ldc + cc] =
                make_float2(acc[mt][nt][0], acc[mt][nt][1]);
            *(float2*)&C[(long)(r0 + 8) * ldc + cc] =
                make_float2(acc[mt][nt][2], acc[mt][nt][3]);
        }
    }
}

// ===========================================================================
// RoPE (in-place): tmp = concat(x[64:], x[:64]), NO negation.
// ===========================================================================
__global__ __launch_bounds__(256)
void rope_kernel(const float* __restrict__ cosb, const float* __restrict__ sinb)
{
    const int s = blockIdx.x;
    const float* cs = cosb + s * 128;
    const float* sn = sinb + s * 128;
    float* row = g_qkv + (long)s * QKV_LD;
    for (int p = threadIdx.x; p < 20 * 64; p += 256) {
        const int head = p >> 6;
        const int d = p & 63;
        float* base = row + head * 128;
        float x0 = base[d];
        float x1 = base[d + 64];
        base[d]      = x0 * cs[d]      + x1 * sn[d];
        base[d + 64] = x1 * cs[d + 64] + x0 * sn[d + 64];
    }
}

// ===========================================================================
// Sliding-window flash attention, tf32 mma.sync, 2D warp tiling.
// 8 warps = 4(M:32 rows) x 2(N half): S = rows x 32 keys; PV = rows x 64 dims.
// Row-max exchanged across warp pairs via smem; l kept warp-partial,
// summed in epilogue. Q/K/P fragments via ldmatrix.
// grid (16 heads, 32 q-blocks of 128), 256 threads.
// ===========================================================================
#define QP 132
#define KP 132
#define VP 136
#define PP 68
#define OFF_K (128 * QP)
#define OFF_V (OFF_K + 64 * KP)
#define OFF_P (OFF_V + 64 * VP)
#define OFF_XM (OFF_P + 128 * PP)
#define OFF_XS (OFF_XM + 256)
#define ATTN_SMEM ((OFF_XS + 256) * 4)

__global__ __launch_bounds__(256, 1)
void attn_tf32()
{
    extern __shared__ float smf[];
    float* Qs = smf;
    float* Ks = smf + OFF_K;
    float* Vs = smf + OFF_V;
    float* Ps = smf + OFF_P;
    float* xm = smf + OFF_XM;   // [128][2] partial row max
    float* xs = smf + OFF_XS;   // [128][2] partial row sum

    const int h  = blockIdx.x;
    const int q0 = (int)(gridDim.y - 1 - blockIdx.y) * 128;
    const int kvh = h >> 2;
    const int tid = threadIdx.x;
    const int w = tid >> 5, lane = tid & 31;
    const int g = lane >> 2, qd = lane & 3;
    const int wm   = (w & 3) * 32;      // 4 M positions
    const int half = w >> 2;            // 0/1: key half (S) and dim half (PV)
    const int kb   = half * 32;         // key base within 64-key tile
    const int db   = half * 64;         // dim base within 128 dims

    // fragment base addresses (ldmatrix; all pitches ≡ 16 mod 128)
    const int at  = lane >> 3;
    const int art = lane & 7;
    const uint32_t qfb = smem_u32(Qs) +
        (uint32_t)((wm + (at & 1) * 8 + art) * QP * 4 + (at >> 1) * 16);
    const uint32_t kfb = smem_u32(Ks) +
        (uint32_t)((kb + art) * KP * 4 + ((lane >> 3) & 1) * 16);
    const uint32_t pfb = smem_u32(Ps) +
        (uint32_t)((wm + (at & 1) * 8 + art) * PP * 4 + (at >> 1) * 16);

    // Q tile: scale + round
    for (int idx = tid; idx < 128 * 32; idx += 256) {
        int r = idx >> 5, c = (idx & 31) * 4;
        float4 v = *(const float4*)(g_qkv + (long)(q0 + r) * QKV_LD + h * 128 + c);
        float* q = Qs + r * QP + c;
        q[0] = to_tf32(v.x * SCALE_F); q[1] = to_tf32(v.y * SCALE_F);
        q[2] = to_tf32(v.z * SCALE_F); q[3] = to_tf32(v.w * SCALE_F);
    }

    float o[2][8][4];
    #pragma unroll
    for (int f = 0; f < 2; f++)
        #pragma unroll
        for (int nt = 0; nt < 8; nt++)
            #pragma unroll
            for (int e = 0; e < 4; e++) o[f][nt][e] = 0.f;
    float m[2][2] = {{-1e30f, -1e30f}, {-1e30f, -1e30f}};
    float l[2][2] = {{0.f, 0.f}, {0.f, 0.f}};

    const int kstart = (q0 >= WIN_) ? q0 - WIN_ : 0;
    const int kend   = q0 + 64;

    for (int k0 = kstart; k0 <= kend; k0 += 64) {
        __syncthreads();   // prior iteration done with Ks/Vs/Ps/xm
        for (int idx = tid; idx < 64 * 32; idx += 256) {
            int r = idx >> 5, c = (idx & 31) * 4;
            const float* src = g_qkv + (long)(k0 + r) * QKV_LD + 2048 + kvh * 128 + c;
            float4 kv = *(const float4*)src;
            float4 vv = *(const float4*)(src + 512);
            float* kd = Ks + r * KP + c;
            kd[0] = to_tf32(kv.x); kd[1] = to_tf32(kv.y);
            kd[2] = to_tf32(kv.z); kd[3] = to_tf32(kv.w);
            float* vd = Vs + r * VP + c;
            vd[0] = to_tf32(vv.x); vd[1] = to_tf32(vv.y);
            vd[2] = to_tf32(vv.z); vd[3] = to_tf32(vv.w);
        }
        __syncthreads();

        // ---- S = Q * K^T : rows wm..wm+31 x keys kb..kb+31 ----
        float s[2][4][4];
        #pragma unroll
        for (int f = 0; f < 2; f++)
            #pragma unroll
            for (int nt = 0; nt < 4; nt++)
                #pragma unroll
                for (int e = 0; e < 4; e++) s[f][nt][e] = 0.f;

        #pragma unroll
        for (int kk = 0; kk < 128; kk += 8) {
            unsigned af0[4], af1[4];
            LDSM_X4(af0[0], af0[1], af0[2], af0[3], qfb + (uint32_t)(kk * 4));
            LDSM_X4(af1[0], af1[1], af1[2], af1[3], qfb + (uint32_t)(16 * QP * 4 + kk * 4));
            #pragma unroll
            for (int nt = 0; nt < 4; nt++) {
                unsigned bf[2];
                LDSM_X2(bf[0], bf[1], kfb + (uint32_t)(nt * 8 * KP * 4 + kk * 4));
                mma_tf32(s[0][nt], af0, bf);
                mma_tf32(s[1][nt], af1, bf);
            }
        }

        // ---- mask + partial row max ----
        float pm[2][2] = {{-1e30f, -1e30f}, {-1e30f, -1e30f}};
        #pragma unroll
        for (int f = 0; f < 2; f++) {
            const int r0 = q0 + wm + f * 16 + g, r1 = r0 + 8;
            #pragma unroll
            for (int nt = 0; nt < 4; nt++) {
                const int j0 = k0 + kb + nt * 8 + 2 * qd;
                const int j1 = j0 + 1;
                if (!(j0 <= r0 && (r0 - j0) < WIN_)) s[f][nt][0] = -1e30f;
                if (!(j1 <= r0 && (r0 - j1) < WIN_)) s[f][nt][1] = -1e30f;
                if (!(j0 <= r1 && (r1 - j0) < WIN_)) s[f][nt][2] = -1e30f;
                if (!(j1 <= r1 && (r1 - j1) < WIN_)) s[f][nt][3] = -1e30f;
                pm[f][0] = fmaxf(pm[f][0], fmaxf(s[f][nt][0], s[f][nt][1]));
                pm[f][1] = fmaxf(pm[f][1], fmaxf(s[f][nt][2], s[f][nt][3]));
            }
            pm[f][0] = fmaxf(pm[f][0], __shfl_xor_sync(0xffffffffu, pm[f][0], 1));
            pm[f][0] = fmaxf(pm[f][0], __shfl_xor_sync(0xffffffffu, pm[f][0], 2));
            pm[f][1] = fmaxf(pm[f][1], __shfl_xor_sync(0xffffffffu, pm[f][1], 1));
            pm[f][1] = fmaxf(pm[f][1], __shfl_xor_sync(0xffffffffu, pm[f][1], 2));
        }

        // ---- exchange partial max across the warp pair ----
        if (qd == 0) {
            xm[(wm + g) * 2 + half]      = pm[0][0];
            xm[(wm + 8 + g) * 2 + half]  = pm[0][1];
            xm[(wm + 16 + g) * 2 + half] = pm[1][0];
            xm[(wm + 24 + g) * 2 + half] = pm[1][1];
        }
        __syncthreads();

        #pragma unroll
        for (int f = 0; f < 2; f++) {
            #pragma unroll
            for (int sbi = 0; sbi < 2; sbi++) {
                const int lr = wm + f * 16 + sbi * 8 + g;
                const float mo = xm[lr * 2 + (half ^ 1)];
                const float mn = fmaxf(m[f][sbi], fmaxf(pm[f][sbi], mo));
                const float sc = __expf(m[f][sbi] - mn);
                float rs = 0.f;
                #pragma unroll
                for (int nt = 0; nt < 4; nt++) {
                    float p0 = __expf(s[f][nt][2 * sbi]     - mn);
                    float p1 = __expf(s[f][nt][2 * sbi + 1] - mn);
                    rs += p0 + p1;
                    *(float2*)&Ps[lr * PP + kb + nt * 8 + 2 * qd] =
                        make_float2(to_tf32(p0), to_tf32(p1));
                }
                rs += __shfl_xor_sync(0xffffffffu, rs, 1);
                rs += __shfl_xor_sync(0xffffffffu, rs, 2);
                l[f][sbi] = l[f][sbi] * sc + rs;
                m[f][sbi] = mn;
                #pragma unroll
                for (int nt = 0; nt < 8; nt++) {
                    o[f][nt][2 * sbi]     *= sc;
                    o[f][nt][2 * sbi + 1] *= sc;
                }
            }
        }
        __syncthreads();   // full P (both halves) visible

        // ---- O += P * V : rows wm..wm+31 x dims db..db+63 ----
        #pragma unroll
        for (int kk = 0; kk < 64; kk += 8) {
            unsigned pa0[4], pa1[4];
            LDSM_X4(pa0[0], pa0[1], pa0[2], pa0[3], pfb + (uint32_t)(kk * 4));
            LDSM_X4(pa1[0], pa1[1], pa1[2], pa1[3], pfb + (uint32_t)(16 * PP * 4 + kk * 4));
            #pragma unroll
            for (int nt = 0; nt < 8; nt++) {
                unsigned bf[2];
                bf[0] = fu(Vs[(kk + qd) * VP + db + nt * 8 + g]);
                bf[1] = fu(Vs[(kk + qd + 4) * VP + db + nt * 8 + g]);
                mma_tf32(o[0][nt], pa0, bf);
                mma_tf32(o[1][nt], pa1, bf);
            }
        }
    }

    // ---- epilogue: combine partial l across pair, normalize, store ----
    if (qd == 0) {
        xs[(wm + g) * 2 + half]      = l[0][0];
        xs[(wm + 8 + g) * 2 + half]  = l[0][1];
        xs[(wm + 16 + g) * 2 + half] = l[1][0];
        xs[(wm + 24 + g) * 2 + half] = l[1][1];
    }
    __syncthreads();

    #pragma unroll
    for (int f = 0; f < 2; f++) {
        const int lr0 = wm + f * 16 + g;
        const float i0 = 1.f / (l[f][0] + xs[lr0 * 2 + (half ^ 1)]);
        const float i1 = 1.f / (l[f][1] + xs[(lr0 + 8) * 2 + (half ^ 1)]);
        #pragma unroll
        for (int nt = 0; nt < 8; nt++) {
            const int cc = h * 128 + db + nt * 8 + 2 * qd;
            *(float2*)&g_attn[(long)(q0 + lr0) * HID + cc] =
                make_float2(to_tf32(o[f][nt][0] * i0), to_tf32(o[f][nt][1] * i0));
            *(float2*)&g_attn[(long)(q0 + lr0 + 8) * HID + cc] =
                make_float2(to_tf32(o[f][nt][2] * i1), to_tf32(o[f][nt][3] * i1));
        }
    }
}

// ===========================================================================
// Launch
// ===========================================================================
extern "C" void kernel_launch(void* const* d_in, const int* in_sizes, int n_in,
                              void* d_out, int out_size)
{
    (void)in_sizes; (void)n_in; (void)out_size;
    const float* hidden = (const float*)d_in[0];
    const float* wq = (const float*)d_in[1];
    const float* wk = (const float*)d_in[2];
    const float* wv = (const float*)d_in[3];
    const float* wo = (const float*)d_in[4];
    const float* cosb = (const float*)d_in[5];
    const float* sinb = (const float*)d_in[6];
    float* out = (float*)d_out;

    void *qkvp, *attnp, *hidrp, *wrp;
    cudaGetSymbolAddress(&qkvp,  g_qkv);
    cudaGetSymbolAddress(&attnp, g_attn);
    cudaGetSymbolAddress(&hidrp, g_hid_r);
    cudaGetSymbolAddress(&wrp,   g_w_r);
    float* qkv   = (float*)qkvp;
    float* attn  = (float*)attnp;
    float* hid_r = (float*)hidrp;
    float* w_r   = (float*)wrp;

    static int attrs_set = 0;
    if (!attrs_set) {
        cudaFuncSetAttribute(gemm_cp,   cudaFuncAttributeMaxDynamicSharedMemorySize, GEMM_SMEM);
        cudaFuncSetAttribute(attn_tf32, cudaFuncAttributeMaxDynamicSharedMemorySize, ATTN_SMEM);
        attrs_set = 1;
    }

    // single fused pre-rounding pass over hidden + 4 weight matrices
    {
        const int n_hid = S_LEN * HID / 4;
        const int n_wq  = 2048 * HID / 4;
        const int n_wkv = 512 * HID / 4;
        const int total = n_hid + n_wq + 2 * n_wkv + n_wq;
        round_all<<<(total + 255) / 256, 256>>>(
            (const float4*)hidden, (float4*)hid_r, n_hid,
            (const float4*)wq, (float4*)(w_r + WQ_OFF), n_wq,
            (const float4*)wk, (float4*)(w_r + WK_OFF), n_wkv,
            (const float4*)wv, (float4*)(w_r + WV_OFF), n_wkv,
            (const float4*)wo, (float4*)(w_r + WO_OFF), n_wq);
    }

    // fused QKV projection: 128-col blocks; wq 16, wk 4, wv 4
    gemm_cp<<<dim3(24, 32), 256, GEMM_SMEM>>>(hid_r, HID,
                                              w_r + WQ_OFF, w_r + WK_OFF, w_r + WV_OFF, HID,
                                              qkv, QKV_LD, HID, 16, 4);

    // RoPE on q and k
    rope_kernel<<<S_LEN, 256>>>(cosb, sinb);

    // sliding-window attention (2D warp-tiled, mma.sync tf32)
    attn_tf32<<<dim3(16, 32), 256, ATTN_SMEM>>>();

    // output projection
    gemm_cp<<<dim3(16, 32), 256, GEMM_SMEM>>>(attn, HID,
                                              w_r + WO_OFF, w_r + WO_OFF, w_r + WO_OFF, HID,
                                              out, HID, HID, 16, 0);
}